// round 12
// baseline (speedup 1.0000x reference)
#include <cuda_runtime.h>
#include <cstdint>
#include <math.h>

// ---------------------------------------------------------------------------
// Problem constants
// ---------------------------------------------------------------------------
constexpr int Bc = 4;
constexpr int Sc = 4096;
constexpr int Dc = 1024;
constexpr int Hc = 16;
constexpr int HDc = 64;
constexpr int Wc = 128;
constexpr int NWIN = Bc * (Sc / Wc);   // 128 windows
constexpr int Mrows = Bc * Sc;         // 16384
constexpr size_t MD = (size_t)Mrows * Dc;
constexpr size_t DD = (size_t)Dc * Dc;

// ---------------------------------------------------------------------------
// Scratch (device globals: allocation-free rule)
// ---------------------------------------------------------------------------
__device__ __align__(128) float g_QKV[3][Mrows * Dc];  // projected Q,K,V
__device__ __align__(128) float g_X[3][Mrows * Dc];    // rounded q,k,v / attn out in [0]
__device__ __align__(128) float g_Wr[4][Dc * Dc];      // rounded+permuted weights
__device__ float g_GO[Bc * 32 * Dc];

// ---------------------------------------------------------------------------
// PTX helpers (baseline ISA: cp.async / mma.sync tf32)
// ---------------------------------------------------------------------------
__device__ __forceinline__ uint32_t smem_to_u32(const void* p) {
    uint32_t a;
    asm("{ .reg .u64 t; cvta.to.shared.u64 t, %1; cvt.u32.u64 %0, t; }"
        : "=r"(a) : "l"(p));
    return a;
}
__device__ __forceinline__ void cp_async16(uint32_t dst, const void* src) {
    asm volatile("cp.async.cg.shared.global [%0], [%1], 16;"
                 :: "r"(dst), "l"(src));
}
#define CP_COMMIT() asm volatile("cp.async.commit_group;" ::: "memory")
#define CP_WAIT(n)  asm volatile("cp.async.wait_group %0;" :: "n"(n) : "memory")

__device__ __forceinline__ float tf32f(float x) {
    uint32_t r;
    asm("cvt.rna.tf32.f32 %0, %1;" : "=r"(r) : "f"(x));
    return __uint_as_float(r);
}
__device__ __forceinline__ uint32_t u32(float x) { return __float_as_uint(x); }

#define MMA_TF32(d, a0v, a1v, a2v, a3v, b0v, b1v) \
    asm volatile("mma.sync.aligned.m16n8k8.row.col.f32.tf32.tf32.f32 " \
        "{%0,%1,%2,%3}, {%4,%5,%6,%7}, {%8,%9}, {%0,%1,%2,%3};" \
        : "+f"((d)[0]), "+f"((d)[1]), "+f"((d)[2]), "+f"((d)[3]) \
        : "r"(a0v), "r"(a1v), "r"(a2v), "r"(a3v), "r"(b0v), "r"(b1v))

// permutation within each 8-element k-group: k -> 2*(k&3) + (k>>2)
__device__ __forceinline__ int permc(int j) { return ((j & 3) << 1) | ((j >> 2) & 1); }

// ---------------------------------------------------------------------------
// Batched fp32 -> tf32-rounded + k-permuted round pass.
// ---------------------------------------------------------------------------
__global__ __launch_bounds__(256) void round_perm_batch_kernel(
    const float* __restrict__ s0, const float* __restrict__ s1,
    const float* __restrict__ s2, const float* __restrict__ s3,
    float* __restrict__ dbase, size_t dstride, int n8)
{
    int i = blockIdx.x * 256 + threadIdx.x;
    if (i >= n8) return;
    const int z = blockIdx.y;
    const float* src = (z == 0) ? s0 : (z == 1) ? s1 : (z == 2) ? s2 : s3;
    float* y = dbase + (size_t)z * dstride;
    const float4* xp = (const float4*)src;
    float4 v0 = xp[2 * i], v1 = xp[2 * i + 1];
    float4 o0, o1;
    o0.x = tf32f(v0.x); o0.y = tf32f(v1.x); o0.z = tf32f(v0.y); o0.w = tf32f(v1.y);
    o1.x = tf32f(v0.z); o1.y = tf32f(v1.z); o1.z = tf32f(v0.w); o1.w = tf32f(v1.w);
    ((float4*)y)[2 * i] = o0;
    ((float4*)y)[2 * i + 1] = o1;
}

// ---------------------------------------------------------------------------
// tf32 mma GEMM: Y[m,n] = sum_k X[m,k]*Wt[n,k] + bias[n]
// Inputs pre-rounded & k-permuted. BM=BN=128, BK=32, 256 threads, 8 warps
// (2x4 grid, 64x32 warp tiles). LDS.64 frags, ROWF=40 pad. 2 CTAs/SM.
// Batched over blockIdx.z: A/Wt/Y by stride arithmetic, bias by ternary.
// ---------------------------------------------------------------------------
constexpr int GBM = 128, GBN = 128, GBK = 32;
constexpr int ROWF = 40;                        // floats per smem row
constexpr int TILE_B = 128 * ROWF * 4;          // 20480 B per matrix tile
constexpr int STAGE_B = 2 * TILE_B;             // 40960
constexpr int SMEM_GEMM = 2 * STAGE_B;          // 81920
constexpr int NCHUNK = Dc / GBK;                // 32

__global__ __launch_bounds__(256, 2) void gemm_tf32_batch_kernel(
    const float* __restrict__ Xbase, const float* __restrict__ Wbase,
    const float* __restrict__ bias0, const float* __restrict__ bias1,
    const float* __restrict__ bias2, float* __restrict__ Ybase)
{
    extern __shared__ __align__(128) char smem[];
    const uint32_t sbase = smem_to_u32(smem);
    const int z = blockIdx.z;
    const float* __restrict__ A = Xbase + (size_t)z * MD;
    const float* __restrict__ Bm = Wbase + (size_t)z * DD;
    const float* __restrict__ bias = (z == 0) ? bias0 : (z == 1) ? bias1 : bias2;
    float* __restrict__ Y = Ybase + (size_t)z * MD;

    const int tid = threadIdx.x;
    const int lane = tid & 31;
    const int wid = tid >> 5;
    const int wm = wid >> 2;        // 0..1 -> 64-row slab
    const int wn = wid & 3;         // 0..3 -> 32-col slab
    const int m0 = blockIdx.y * GBM;
    const int n0 = blockIdx.x * GBN;
    const int g = lane >> 2;        // 0..7
    const int t = lane & 3;         // 0..3

    float acc[4][4][4];
#pragma unroll
    for (int mi = 0; mi < 4; mi++)
#pragma unroll
        for (int nt = 0; nt < 4; nt++)
#pragma unroll
            for (int e = 0; e < 4; e++) acc[mi][nt][e] = 0.f;

    auto issue = [&](int c, int s) {
        const int k0 = c * GBK;
        const uint32_t sb = sbase + s * STAGE_B;
#pragma unroll
        for (int i = 0; i < 4; i++) {               // A: 128 rows x 8 chunks
            int idx = tid + i * 256;                // 0..1023
            int r = idx >> 3, ch = idx & 7;
            cp_async16(sb + r * (ROWF * 4) + ch * 16,
                       A + (size_t)(m0 + r) * Dc + k0 + ch * 4);
        }
#pragma unroll
        for (int i = 0; i < 4; i++) {               // B
            int idx = tid + i * 256;
            int r = idx >> 3, ch = idx & 7;
            cp_async16(sb + TILE_B + r * (ROWF * 4) + ch * 16,
                       Bm + (size_t)(n0 + r) * Dc + k0 + ch * 4);
        }
        CP_COMMIT();
    };

    issue(0, 0);
    issue(1, 1);

    for (int c = 0; c < NCHUNK; c++) {
        const int s = c & 1;
        if (c < NCHUNK - 2) { CP_WAIT(1); } else { CP_WAIT(0); }
        __syncthreads();

        const float* As = (const float*)(smem + s * STAGE_B);
        const float* Bs = (const float*)(smem + s * STAGE_B + TILE_B);

#pragma unroll
        for (int ks = 0; ks < 4; ks++) {
            const int kk = ks * 8;
            float2 bf[4];
#pragma unroll
            for (int nt = 0; nt < 4; nt++)
                bf[nt] = *(const float2*)&Bs[(wn * 32 + nt * 8 + g) * ROWF + kk + 2 * t];
#pragma unroll
            for (int mi = 0; mi < 4; mi++) {
                const int mr = wm * 64 + mi * 16 + g;
                float2 a0 = *(const float2*)&As[mr * ROWF + kk + 2 * t];
                float2 a1 = *(const float2*)&As[(mr + 8) * ROWF + kk + 2 * t];
#pragma unroll
                for (int nt = 0; nt < 4; nt++)
                    MMA_TF32(acc[mi][nt], u32(a0.x), u32(a1.x), u32(a0.y), u32(a1.y),
                             u32(bf[nt].x), u32(bf[nt].y));
            }
        }
        __syncthreads();
        if (c + 2 < NCHUNK) issue(c + 2, s);
    }

    // Epilogue: registers -> gmem with fused bias (float2, coalesced)
#pragma unroll
    for (int nt = 0; nt < 4; nt++) {
        const int n = n0 + wn * 32 + nt * 8 + 2 * t;
        const float b0 = bias[n], b1 = bias[n + 1];
#pragma unroll
        for (int mi = 0; mi < 4; mi++) {
            const int r0 = m0 + wm * 64 + mi * 16 + g;
            float2 v0, v1;
            v0.x = acc[mi][nt][0] + b0; v0.y = acc[mi][nt][1] + b1;
            v1.x = acc[mi][nt][2] + b0; v1.y = acc[mi][nt][3] + b1;
            *(float2*)&Y[(size_t)r0 * Dc + n] = v0;
            *(float2*)&Y[(size_t)(r0 + 8) * Dc + n] = v1;
        }
    }
}

// ---------------------------------------------------------------------------
// Windowed attention via tensor cores — SPLIT-Q version.
// grid (NWIN, H, 2): blockIdx.z selects 64 Q-rows; 128 threads (4 warps x 16
// rows). All 128 keys per CTA. Smem 106 KB -> 2 CTAs/SM (staging of one CTA
// hides under compute of the other). Ps reuses the dead Qh/Ql region (guarded
// by one __syncthreads). Per-row numerics identical to the 1-CTA version.
// ---------------------------------------------------------------------------
constexpr int QSTR = 72;    // row stride (floats) for Qh/Ql/Ks
constexpr int VSTR = 136;   // row stride for Vs [d][key]
constexpr int PSTR = 136;   // row stride for Ps [row][key]
constexpr int OFF_QH = 0;                        // 64 x QSTR
constexpr int OFF_QL = OFF_QH + 64 * QSTR;       // 4608
constexpr int OFF_K  = OFF_QL + 64 * QSTR;       // 9216  (128 x QSTR)
constexpr int OFF_V  = OFF_K + 128 * QSTR;       // 18432 (64 x VSTR)
constexpr int OFF_P  = OFF_QH;                   // Ps overlays Qh+Ql (64x136 <= 128x72)
constexpr int SMEM_ATTN = (OFF_V + 64 * VSTR) * 4;   // 108544 B

__global__ __launch_bounds__(128, 2) void window_attn_mma_kernel(
    const float* __restrict__ Qp, const float* __restrict__ Kp,
    const float* __restrict__ Vp, float* __restrict__ Xr)
{
    extern __shared__ __align__(16) float sm[];
    float* Qh = sm + OFF_QH;
    float* Ql = sm + OFF_QL;
    float* Ks = sm + OFF_K;
    float* Vs = sm + OFF_V;
    float* Ps = sm + OFF_P;

    const int win = blockIdx.x;
    const int h = blockIdx.y;
    const int qhalf = blockIdx.z;               // 0 or 1: which 64 Q-rows
    const size_t base = (size_t)win * Wc * Dc + h * HDc;
    const int tid = threadIdx.x;

    // Stage K, V (all 128 keys)
    for (int idx = tid; idx < Wc * HDc; idx += 128) {
        int row = idx >> 6, col = idx & 63;
        int pc = (col & ~7) | permc(col & 7);
        size_t ga = base + (size_t)row * Dc + col;
        Ks[row * QSTR + pc] = tf32f(Kp[ga]);
        int pk = (row & ~7) | permc(row & 7);
        Vs[col * VSTR + pk] = tf32f(Vp[ga]);
    }
    // Stage Q (this CTA's 64 rows), hi/lo split
    for (int idx = tid; idx < 64 * HDc; idx += 128) {
        int lr = idx >> 6, col = idx & 63;
        int pc = (col & ~7) | permc(col & 7);
        size_t ga = base + (size_t)(qhalf * 64 + lr) * Dc + col;
        float q = Qp[ga];
        float hi = tf32f(q);
        Qh[lr * QSTR + pc] = hi;
        Ql[lr * QSTR + pc] = tf32f(q - hi);
    }
    __syncthreads();

    const int w = tid >> 5;                     // 0..3
    const int lane = tid & 31;
    const int g = lane >> 2, t = lane & 3;
    const int lr0 = w * 16 + g, lr1 = lr0 + 8;  // local Q rows (0..63)
    const int pc0 = permc(2 * t), pc1 = permc(2 * t + 1);

    // ---- S = Q*K^T (2-pass: Qhi + Qlo) ----
    float sa[16][4];
#pragma unroll
    for (int nt = 0; nt < 16; nt++)
#pragma unroll
        for (int e = 0; e < 4; e++) sa[nt][e] = 0.f;

#pragma unroll
    for (int kt = 0; kt < 8; kt++) {
        const int kk = kt * 8 + 2 * t;
        float2 ah0 = *(const float2*)&Qh[lr0 * QSTR + kk];
        float2 ah1 = *(const float2*)&Qh[lr1 * QSTR + kk];
        float2 al0 = *(const float2*)&Ql[lr0 * QSTR + kk];
        float2 al1 = *(const float2*)&Ql[lr1 * QSTR + kk];
#pragma unroll
        for (int nt = 0; nt < 16; nt++) {
            float2 b = *(const float2*)&Ks[(nt * 8 + g) * QSTR + kk];
            MMA_TF32(sa[nt], u32(ah0.x), u32(ah1.x), u32(ah0.y), u32(ah1.y),
                     u32(b.x), u32(b.y));
            MMA_TF32(sa[nt], u32(al0.x), u32(al1.x), u32(al0.y), u32(al1.y),
                     u32(b.x), u32(b.y));
        }
    }

    // All warps finished reading Qh/Ql — safe to overlay Ps on that region.
    __syncthreads();

    // ---- softmax (rows lr0, lr1) ----
    float mx0 = -1e30f, mx1 = -1e30f;
#pragma unroll
    for (int nt = 0; nt < 16; nt++) {
#pragma unroll
        for (int e = 0; e < 4; e++) sa[nt][e] *= 0.125f;
        mx0 = fmaxf(mx0, fmaxf(sa[nt][0], sa[nt][1]));
        mx1 = fmaxf(mx1, fmaxf(sa[nt][2], sa[nt][3]));
    }
    mx0 = fmaxf(mx0, __shfl_xor_sync(0xffffffffu, mx0, 1));
    mx0 = fmaxf(mx0, __shfl_xor_sync(0xffffffffu, mx0, 2));
    mx1 = fmaxf(mx1, __shfl_xor_sync(0xffffffffu, mx1, 1));
    mx1 = fmaxf(mx1, __shfl_xor_sync(0xffffffffu, mx1, 2));

    float l0 = 0.f, l1 = 0.f;
#pragma unroll
    for (int nt = 0; nt < 16; nt++) {
        float p00 = __expf(sa[nt][0] - mx0);
        float p01 = __expf(sa[nt][1] - mx0);
        float p10 = __expf(sa[nt][2] - mx1);
        float p11 = __expf(sa[nt][3] - mx1);
        l0 += p00 + p01;
        l1 += p10 + p11;
        Ps[lr0 * PSTR + nt * 8 + pc0] = tf32f(p00);
        Ps[lr0 * PSTR + nt * 8 + pc1] = tf32f(p01);
        Ps[lr1 * PSTR + nt * 8 + pc0] = tf32f(p10);
        Ps[lr1 * PSTR + nt * 8 + pc1] = tf32f(p11);
    }
    l0 += __shfl_xor_sync(0xffffffffu, l0, 1);
    l0 += __shfl_xor_sync(0xffffffffu, l0, 2);
    l1 += __shfl_xor_sync(0xffffffffu, l1, 1);
    l1 += __shfl_xor_sync(0xffffffffu, l1, 2);
    __syncwarp();

    // ---- O = P*V ----
    float oa[8][4];
#pragma unroll
    for (int nt = 0; nt < 8; nt++)
#pragma unroll
        for (int e = 0; e < 4; e++) oa[nt][e] = 0.f;

#pragma unroll
    for (int kt = 0; kt < 16; kt++) {
        const int kk = kt * 8 + 2 * t;
        float2 a0 = *(const float2*)&Ps[lr0 * PSTR + kk];
        float2 a1 = *(const float2*)&Ps[lr1 * PSTR + kk];
#pragma unroll
        for (int nt = 0; nt < 8; nt++) {
            float2 b = *(const float2*)&Vs[(nt * 8 + g) * VSTR + kk];
            MMA_TF32(oa[nt], u32(a0.x), u32(a1.x), u32(a0.y), u32(a1.y),
                     u32(b.x), u32(b.y));
        }
    }

    const float inv0 = 1.f / l0, inv1 = 1.f / l1;
    float* o0p = Xr + (size_t)(win * Wc + qhalf * 64 + lr0) * Dc + h * HDc;
    float* o1p = Xr + (size_t)(win * Wc + qhalf * 64 + lr1) * Dc + h * HDc;
#pragma unroll
    for (int nt = 0; nt < 8; nt++) {
        o0p[nt * 8 + pc0] = tf32f(oa[nt][0] * inv0);
        o0p[nt * 8 + pc1] = tf32f(oa[nt][1] * inv0);
        o1p[nt * 8 + pc0] = tf32f(oa[nt][2] * inv1);
        o1p[nt * 8 + pc1] = tf32f(oa[nt][3] * inv1);
    }
}

// ---------------------------------------------------------------------------
// Global attention over 32 gathered tokens (fp32 exact). grid (B, H), 32 thr.
// ---------------------------------------------------------------------------
__global__ __launch_bounds__(32) void global_attn_kernel(
    const float* __restrict__ Qp, const float* __restrict__ Kp,
    const float* __restrict__ Vp, const int* __restrict__ gidx,
    float* __restrict__ GO)
{
    __shared__ __align__(16) float Ks[32 * 64];
    __shared__ __align__(16) float Vs[32 * 64];
    __shared__ int sidx[32];

    const int b = blockIdx.x, h = blockIdx.y, tid = threadIdx.x;
    sidx[tid] = gidx[tid];
    __syncthreads();

    for (int idx = tid; idx < 32 * 64; idx += 32) {
        int rr = idx >> 6, c = idx & 63;
        size_t gg = ((size_t)b * Sc + sidx[rr]) * Dc + h * HDc + c;
        Ks[idx] = Kp[gg];
        Vs[idx] = Vp[gg];
    }
    __syncthreads();

    const int i = tid;
    size_t qoff = ((size_t)b * Sc + sidx[i]) * Dc + h * HDc;
    float q[64];
#pragma unroll
    for (int d = 0; d < 64; d++) q[d] = Qp[qoff + d];

    float s[32];
    float mx = -1e30f;
    for (int j = 0; j < 32; j++) {
        float a = 0.f;
#pragma unroll
        for (int d = 0; d < 64; d++) a += q[d] * Ks[j * 64 + d];
        a *= 0.125f;
        s[j] = a;
        mx = fmaxf(mx, a);
    }
    float l = 0.f;
    for (int j = 0; j < 32; j++) { s[j] = __expf(s[j] - mx); l += s[j]; }

    float acc[64];
#pragma unroll
    for (int d = 0; d < 64; d++) acc[d] = 0.f;
    for (int j = 0; j < 32; j++) {
        float p = s[j];
#pragma unroll
        for (int d = 0; d < 64; d++) acc[d] += p * Vs[j * 64 + d];
    }
    float inv = 1.f / l;
    float* o = GO + ((size_t)(b * 32 + i)) * Dc + h * HDc;
#pragma unroll
    for (int d = 0; d < 64; d++) o[d] = acc[d] * inv;
}

// ---------------------------------------------------------------------------
// Project 128 global rows with Wo (fp32 exact), scatter into Y.
// ---------------------------------------------------------------------------
__global__ __launch_bounds__(256) void global_proj_kernel(
    const float* __restrict__ GO, const float* __restrict__ Wo,
    const float* __restrict__ bo, const int* __restrict__ gidx,
    float* __restrict__ Y)
{
    __shared__ __align__(16) float xr[Dc];
    const int row = blockIdx.x;
    const int nb = blockIdx.y;
    const int tid = threadIdx.x;

    for (int i = tid; i < Dc; i += 256) xr[i] = GO[(size_t)row * Dc + i];
    __syncthreads();

    const int n = nb * 256 + tid;
    const float4* wr = (const float4*)(Wo + (size_t)n * Dc);
    const float4* x4 = (const float4*)xr;
    float s0 = 0.f, s1 = 0.f, s2 = 0.f, s3 = 0.f;
#pragma unroll 8
    for (int k = 0; k < Dc / 4; k++) {
        float4 w = wr[k];
        float4 x = x4[k];
        s0 += w.x * x.x; s1 += w.y * x.y; s2 += w.z * x.z; s3 += w.w * x.w;
    }
    float sum = s0 + s1 + s2 + s3 + bo[n];

    const int b = row >> 5, i = row & 31;
    const int tok = gidx[i];
    Y[((size_t)b * Sc + tok) * Dc + n] = sum;
}

// ---------------------------------------------------------------------------
extern "C" void kernel_launch(void* const* d_in, const int* in_sizes, int n_in,
                              void* d_out, int out_size)
{
    const float* query = (const float*)d_in[0];
    const float* key   = (const float*)d_in[1];
    const float* value = (const float*)d_in[2];
    const float* Wq = (const float*)d_in[3];
    const float* bq = (const float*)d_in[4];
    const float* Wk = (const float*)d_in[5];
    const float* bk = (const float*)d_in[6];
    const float* Wv = (const float*)d_in[7];
    const float* bv = (const float*)d_in[8];
    const float* Wo = (const float*)d_in[9];
    const float* bo = (const float*)d_in[10];
    const int* gidx = (const int*)d_in[11];
    float* out = (float*)d_out;

    float *QKVb, *Xb, *Wr, *GOb;
    cudaGetSymbolAddress((void**)&QKVb, g_QKV);
    cudaGetSymbolAddress((void**)&Xb, g_X);
    cudaGetSymbolAddress((void**)&Wr, g_Wr);
    cudaGetSymbolAddress((void**)&GOb, g_GO);
    float* Qb = QKVb;
    float* Kb = QKVb + MD;
    float* Vb = QKVb + 2 * MD;

    cudaFuncSetAttribute(gemm_tf32_batch_kernel,
                         cudaFuncAttributeMaxDynamicSharedMemorySize, SMEM_GEMM);
    cudaFuncSetAttribute(window_attn_mma_kernel,
                         cudaFuncAttributeMaxDynamicSharedMemorySize, SMEM_ATTN);

    const int WN8 = (int)(DD / 8);
    const int XN8 = (int)(MD / 8);
    const int WGRID = (WN8 + 255) / 256;
    const int XGRID = (XN8 + 255) / 256;

    // Round the 4 weights (one launch, y=4): dst = Wr + z*DD
    round_perm_batch_kernel<<<dim3(WGRID, 4), 256>>>(
        Wq, Wk, Wv, Wo, Wr, DD, WN8);

    // Round the 3 activations (one launch, y=3): dst = Xb + z*MD
    round_perm_batch_kernel<<<dim3(XGRID, 3), 256>>>(
        query, key, value, query, Xb, MD, XN8);

    // Q/K/V projections in ONE batched launch (z=3)
    gemm_tf32_batch_kernel<<<dim3(Dc / GBN, Mrows / GBM, 3), 256, SMEM_GEMM>>>(
        Xb, Wr, bq, bk, bv, QKVb);

    // Windowed attention (split-Q: 2 CTAs per (window, head))
    window_attn_mma_kernel<<<dim3(NWIN, Hc, 2), 128, SMEM_ATTN>>>(Qb, Kb, Vb, Xb);

    // Global attention on gathered tokens (tiny; QKV ready)
    global_attn_kernel<<<dim3(Bc, Hc), 32>>>(Qb, Kb, Vb, gidx, GOb);

    // Output projection (z=1: A = Xb[0], Wt = Wr[3], Y = out)
    gemm_tf32_batch_kernel<<<dim3(Dc / GBN, Mrows / GBM, 1), 256, SMEM_GEMM>>>(
        Xb, Wr + 3 * DD, bo, bo, bo, out);

    // Global scatter must follow the final GEMM (overwrites its rows)
    global_proj_kernel<<<dim3(Bc * 32, Dc / 256), 256>>>(GOb, Wo, bo, gidx, out);
}

// round 13
// speedup vs baseline: 1.1115x; 1.1115x over previous
#include <cuda_runtime.h>
#include <cstdint>
#include <math.h>

// ---------------------------------------------------------------------------
// Problem constants
// ---------------------------------------------------------------------------
constexpr int Bc = 4;
constexpr int Sc = 4096;
constexpr int Dc = 1024;
constexpr int Hc = 16;
constexpr int HDc = 64;
constexpr int Wc = 128;
constexpr int NWIN = Bc * (Sc / Wc);   // 128 windows
constexpr int Mrows = Bc * Sc;         // 16384
constexpr size_t MD = (size_t)Mrows * Dc;
constexpr size_t DD = (size_t)Dc * Dc;

// ---------------------------------------------------------------------------
// Scratch (device globals: allocation-free rule)
// ---------------------------------------------------------------------------
__device__ __align__(128) float g_QKV[3][Mrows * Dc];  // projected Q,K,V
__device__ __align__(128) float g_X[3][Mrows * Dc];    // rounded q,k,v / attn out in [0]
__device__ __align__(128) float g_Wr[4][Dc * Dc];      // rounded+permuted weights
__device__ float g_GO[Bc * 32 * Dc];

// ---------------------------------------------------------------------------
// PTX helpers (baseline ISA: cp.async / mma.sync tf32)
// ---------------------------------------------------------------------------
__device__ __forceinline__ uint32_t smem_to_u32(const void* p) {
    uint32_t a;
    asm("{ .reg .u64 t; cvta.to.shared.u64 t, %1; cvt.u32.u64 %0, t; }"
        : "=r"(a) : "l"(p));
    return a;
}
__device__ __forceinline__ void cp_async16(uint32_t dst, const void* src) {
    asm volatile("cp.async.cg.shared.global [%0], [%1], 16;"
                 :: "r"(dst), "l"(src));
}
#define CP_COMMIT() asm volatile("cp.async.commit_group;" ::: "memory")
#define CP_WAIT(n)  asm volatile("cp.async.wait_group %0;" :: "n"(n) : "memory")

__device__ __forceinline__ float tf32f(float x) {
    uint32_t r;
    asm("cvt.rna.tf32.f32 %0, %1;" : "=r"(r) : "f"(x));
    return __uint_as_float(r);
}
__device__ __forceinline__ uint32_t u32(float x) { return __float_as_uint(x); }

#define MMA_TF32(d, a0v, a1v, a2v, a3v, b0v, b1v) \
    asm volatile("mma.sync.aligned.m16n8k8.row.col.f32.tf32.tf32.f32 " \
        "{%0,%1,%2,%3}, {%4,%5,%6,%7}, {%8,%9}, {%0,%1,%2,%3};" \
        : "+f"((d)[0]), "+f"((d)[1]), "+f"((d)[2]), "+f"((d)[3]) \
        : "r"(a0v), "r"(a1v), "r"(a2v), "r"(a3v), "r"(b0v), "r"(b1v))

// permutation within each 8-element k-group: k -> 2*(k&3) + (k>>2)
__device__ __forceinline__ int permc(int j) { return ((j & 3) << 1) | ((j >> 2) & 1); }

// ---------------------------------------------------------------------------
// Batched fp32 -> tf32-rounded + k-permuted round pass.
// ---------------------------------------------------------------------------
__global__ __launch_bounds__(256) void round_perm_batch_kernel(
    const float* __restrict__ s0, const float* __restrict__ s1,
    const float* __restrict__ s2, const float* __restrict__ s3,
    float* __restrict__ dbase, size_t dstride, int n8)
{
    int i = blockIdx.x * 256 + threadIdx.x;
    if (i >= n8) return;
    const int z = blockIdx.y;
    const float* src = (z == 0) ? s0 : (z == 1) ? s1 : (z == 2) ? s2 : s3;
    float* y = dbase + (size_t)z * dstride;
    const float4* xp = (const float4*)src;
    float4 v0 = xp[2 * i], v1 = xp[2 * i + 1];
    float4 o0, o1;
    o0.x = tf32f(v0.x); o0.y = tf32f(v1.x); o0.z = tf32f(v0.y); o0.w = tf32f(v1.y);
    o1.x = tf32f(v0.z); o1.y = tf32f(v1.z); o1.z = tf32f(v0.w); o1.w = tf32f(v1.w);
    ((float4*)y)[2 * i] = o0;
    ((float4*)y)[2 * i + 1] = o1;
}

// ---------------------------------------------------------------------------
// tf32 mma GEMM: Y[m,n] = sum_k X[m,k]*Wt[n,k] + bias[n]
// Inputs pre-rounded & k-permuted. BM=BN=128, BK=32, 256 threads, 8 warps
// (2x4 grid, 64x32 warp tiles). LDS.64 frags, ROWF=40 pad. 2 CTAs/SM.
// Batched over blockIdx.z: A/Wt/Y by stride arithmetic, bias by ternary.
// ---------------------------------------------------------------------------
constexpr int GBM = 128, GBN = 128, GBK = 32;
constexpr int ROWF = 40;                        // floats per smem row
constexpr int TILE_B = 128 * ROWF * 4;          // 20480 B per matrix tile
constexpr int STAGE_B = 2 * TILE_B;             // 40960
constexpr int SMEM_GEMM = 2 * STAGE_B;          // 81920
constexpr int NCHUNK = Dc / GBK;                // 32

__global__ __launch_bounds__(256, 2) void gemm_tf32_batch_kernel(
    const float* __restrict__ Xbase, const float* __restrict__ Wbase,
    const float* __restrict__ bias0, const float* __restrict__ bias1,
    const float* __restrict__ bias2, float* __restrict__ Ybase)
{
    extern __shared__ __align__(128) char smem[];
    const uint32_t sbase = smem_to_u32(smem);
    const int z = blockIdx.z;
    const float* __restrict__ A = Xbase + (size_t)z * MD;
    const float* __restrict__ Bm = Wbase + (size_t)z * DD;
    const float* __restrict__ bias = (z == 0) ? bias0 : (z == 1) ? bias1 : bias2;
    float* __restrict__ Y = Ybase + (size_t)z * MD;

    const int tid = threadIdx.x;
    const int lane = tid & 31;
    const int wid = tid >> 5;
    const int wm = wid >> 2;        // 0..1 -> 64-row slab
    const int wn = wid & 3;         // 0..3 -> 32-col slab
    const int m0 = blockIdx.y * GBM;
    const int n0 = blockIdx.x * GBN;
    const int g = lane >> 2;        // 0..7
    const int t = lane & 3;         // 0..3

    float acc[4][4][4];
#pragma unroll
    for (int mi = 0; mi < 4; mi++)
#pragma unroll
        for (int nt = 0; nt < 4; nt++)
#pragma unroll
            for (int e = 0; e < 4; e++) acc[mi][nt][e] = 0.f;

    auto issue = [&](int c, int s) {
        const int k0 = c * GBK;
        const uint32_t sb = sbase + s * STAGE_B;
#pragma unroll
        for (int i = 0; i < 4; i++) {               // A: 128 rows x 8 chunks
            int idx = tid + i * 256;                // 0..1023
            int r = idx >> 3, ch = idx & 7;
            cp_async16(sb + r * (ROWF * 4) + ch * 16,
                       A + (size_t)(m0 + r) * Dc + k0 + ch * 4);
        }
#pragma unroll
        for (int i = 0; i < 4; i++) {               // B
            int idx = tid + i * 256;
            int r = idx >> 3, ch = idx & 7;
            cp_async16(sb + TILE_B + r * (ROWF * 4) + ch * 16,
                       Bm + (size_t)(n0 + r) * Dc + k0 + ch * 4);
        }
        CP_COMMIT();
    };

    issue(0, 0);
    issue(1, 1);

    for (int c = 0; c < NCHUNK; c++) {
        const int s = c & 1;
        if (c < NCHUNK - 2) { CP_WAIT(1); } else { CP_WAIT(0); }
        __syncthreads();

        const float* As = (const float*)(smem + s * STAGE_B);
        const float* Bs = (const float*)(smem + s * STAGE_B + TILE_B);

#pragma unroll
        for (int ks = 0; ks < 4; ks++) {
            const int kk = ks * 8;
            float2 bf[4];
#pragma unroll
            for (int nt = 0; nt < 4; nt++)
                bf[nt] = *(const float2*)&Bs[(wn * 32 + nt * 8 + g) * ROWF + kk + 2 * t];
#pragma unroll
            for (int mi = 0; mi < 4; mi++) {
                const int mr = wm * 64 + mi * 16 + g;
                float2 a0 = *(const float2*)&As[mr * ROWF + kk + 2 * t];
                float2 a1 = *(const float2*)&As[(mr + 8) * ROWF + kk + 2 * t];
#pragma unroll
                for (int nt = 0; nt < 4; nt++)
                    MMA_TF32(acc[mi][nt], u32(a0.x), u32(a1.x), u32(a0.y), u32(a1.y),
                             u32(bf[nt].x), u32(bf[nt].y));
            }
        }
        __syncthreads();
        if (c + 2 < NCHUNK) issue(c + 2, s);
    }

    // Epilogue: registers -> gmem with fused bias (float2, coalesced)
#pragma unroll
    for (int nt = 0; nt < 4; nt++) {
        const int n = n0 + wn * 32 + nt * 8 + 2 * t;
        const float b0 = bias[n], b1 = bias[n + 1];
#pragma unroll
        for (int mi = 0; mi < 4; mi++) {
            const int r0 = m0 + wm * 64 + mi * 16 + g;
            float2 v0, v1;
            v0.x = acc[mi][nt][0] + b0; v0.y = acc[mi][nt][1] + b1;
            v1.x = acc[mi][nt][2] + b0; v1.y = acc[mi][nt][3] + b1;
            *(float2*)&Y[(size_t)r0 * Dc + n] = v0;
            *(float2*)&Y[(size_t)(r0 + 8) * Dc + n] = v1;
        }
    }
}

// ---------------------------------------------------------------------------
// Windowed attention via tensor cores (R11 monolithic config, float4 staging).
// grid (NWIN, H), 256 threads (8 warps, 16 Q-rows each). Single 128-key
// block: exact softmax. S = Q*K^T 2-pass split-Q tf32 mma; P via smem;
// O = P*V. Output tf32-rounded + k-permuted into Xr for the final GEMM.
// ---------------------------------------------------------------------------
constexpr int QSTR = 72;    // row stride (floats) for Qh/Ql/Ks  [row][d]
constexpr int VSTR = 136;   // row stride for Vs [d][key]
constexpr int PSTR = 136;   // row stride for Ps [row][key]
constexpr int OFF_QH = 0;
constexpr int OFF_QL = OFF_QH + 128 * QSTR;     // 9216
constexpr int OFF_K  = OFF_QL + 128 * QSTR;     // 18432
constexpr int OFF_V  = OFF_K + 128 * QSTR;      // 27648
constexpr int OFF_P  = OFF_V + 64 * VSTR;       // 36352
constexpr int SMEM_ATTN = (OFF_P + 128 * PSTR) * 4;  // 215040 B

__global__ __launch_bounds__(256, 1) void window_attn_mma_kernel(
    const float* __restrict__ Qp, const float* __restrict__ Kp,
    const float* __restrict__ Vp, float* __restrict__ Xr)
{
    extern __shared__ __align__(16) float sm[];
    float* Qh = sm + OFF_QH;
    float* Ql = sm + OFF_QL;
    float* Ks = sm + OFF_K;
    float* Vs = sm + OFF_V;
    float* Ps = sm + OFF_P;

    const int win = blockIdx.x;
    const int h = blockIdx.y;
    const size_t base = (size_t)win * Wc * Dc + h * HDc;
    const int tid = threadIdx.x;

    // Stage Q (hi/lo split), K, V — float4 loads, tf32 rounding, permuted STS.
    // Each 4-aligned column quad stays inside one 8-column perm group:
    // pc = (col4 & ~7) | (col4&4 ? 1 : 0) + 2i  ==  (col&~7)|permc(col&7).
#pragma unroll
    for (int it = 0; it < 8; it++) {
        int idx = tid + it * 256;                // 0..2047
        int row = idx >> 4;                      // 0..127
        int col4 = (idx & 15) << 2;              // 0,4,...,60
        int pcb = (col4 & ~7) | ((col4 & 4) ? 1 : 0);
        size_t ga = base + (size_t)row * Dc + col4;
        float4 qv = *(const float4*)(Qp + ga);
        float4 kv = *(const float4*)(Kp + ga);
        float4 vv = *(const float4*)(Vp + ga);

        float h0 = tf32f(qv.x), h1 = tf32f(qv.y);
        float h2 = tf32f(qv.z), h3 = tf32f(qv.w);
        float* qh = &Qh[row * QSTR + pcb];
        float* ql = &Ql[row * QSTR + pcb];
        float* ks = &Ks[row * QSTR + pcb];
        qh[0] = h0; qh[2] = h1; qh[4] = h2; qh[6] = h3;
        ql[0] = tf32f(qv.x - h0); ql[2] = tf32f(qv.y - h1);
        ql[4] = tf32f(qv.z - h2); ql[6] = tf32f(qv.w - h3);
        ks[0] = tf32f(kv.x); ks[2] = tf32f(kv.y);
        ks[4] = tf32f(kv.z); ks[6] = tf32f(kv.w);

        int pk = (row & ~7) | permc(row & 7);
        Vs[(col4 + 0) * VSTR + pk] = tf32f(vv.x);
        Vs[(col4 + 1) * VSTR + pk] = tf32f(vv.y);
        Vs[(col4 + 2) * VSTR + pk] = tf32f(vv.z);
        Vs[(col4 + 3) * VSTR + pk] = tf32f(vv.w);
    }
    __syncthreads();

    const int w = tid >> 5;
    const int lane = tid & 31;
    const int g = lane >> 2, t = lane & 3;
    const int r0 = w * 16 + g, r1 = r0 + 8;
    const int pc0 = permc(2 * t), pc1 = permc(2 * t + 1);

    // ---- S = Q*K^T (2-pass: Qhi + Qlo) ----
    float sa[16][4];
#pragma unroll
    for (int nt = 0; nt < 16; nt++)
#pragma unroll
        for (int e = 0; e < 4; e++) sa[nt][e] = 0.f;

#pragma unroll
    for (int kt = 0; kt < 8; kt++) {
        const int kk = kt * 8 + 2 * t;
        float2 ah0 = *(const float2*)&Qh[r0 * QSTR + kk];
        float2 ah1 = *(const float2*)&Qh[r1 * QSTR + kk];
        float2 al0 = *(const float2*)&Ql[r0 * QSTR + kk];
        float2 al1 = *(const float2*)&Ql[r1 * QSTR + kk];
#pragma unroll
        for (int nt = 0; nt < 16; nt++) {
            float2 b = *(const float2*)&Ks[(nt * 8 + g) * QSTR + kk];
            MMA_TF32(sa[nt], u32(ah0.x), u32(ah1.x), u32(ah0.y), u32(ah1.y),
                     u32(b.x), u32(b.y));
            MMA_TF32(sa[nt], u32(al0.x), u32(al1.x), u32(al0.y), u32(al1.y),
                     u32(b.x), u32(b.y));
        }
    }

    // ---- softmax (rows r0, r1) ----
    float mx0 = -1e30f, mx1 = -1e30f;
#pragma unroll
    for (int nt = 0; nt < 16; nt++) {
#pragma unroll
        for (int e = 0; e < 4; e++) sa[nt][e] *= 0.125f;
        mx0 = fmaxf(mx0, fmaxf(sa[nt][0], sa[nt][1]));
        mx1 = fmaxf(mx1, fmaxf(sa[nt][2], sa[nt][3]));
    }
    mx0 = fmaxf(mx0, __shfl_xor_sync(0xffffffffu, mx0, 1));
    mx0 = fmaxf(mx0, __shfl_xor_sync(0xffffffffu, mx0, 2));
    mx1 = fmaxf(mx1, __shfl_xor_sync(0xffffffffu, mx1, 1));
    mx1 = fmaxf(mx1, __shfl_xor_sync(0xffffffffu, mx1, 2));

    float l0 = 0.f, l1 = 0.f;
#pragma unroll
    for (int nt = 0; nt < 16; nt++) {
        float p00 = __expf(sa[nt][0] - mx0);
        float p01 = __expf(sa[nt][1] - mx0);
        float p10 = __expf(sa[nt][2] - mx1);
        float p11 = __expf(sa[nt][3] - mx1);
        l0 += p00 + p01;
        l1 += p10 + p11;
        Ps[r0 * PSTR + nt * 8 + pc0] = tf32f(p00);
        Ps[r0 * PSTR + nt * 8 + pc1] = tf32f(p01);
        Ps[r1 * PSTR + nt * 8 + pc0] = tf32f(p10);
        Ps[r1 * PSTR + nt * 8 + pc1] = tf32f(p11);
    }
    l0 += __shfl_xor_sync(0xffffffffu, l0, 1);
    l0 += __shfl_xor_sync(0xffffffffu, l0, 2);
    l1 += __shfl_xor_sync(0xffffffffu, l1, 1);
    l1 += __shfl_xor_sync(0xffffffffu, l1, 2);
    __syncwarp();

    // ---- O = P*V ----
    float oa[8][4];
#pragma unroll
    for (int nt = 0; nt < 8; nt++)
#pragma unroll
        for (int e = 0; e < 4; e++) oa[nt][e] = 0.f;

#pragma unroll
    for (int kt = 0; kt < 16; kt++) {
        const int kk = kt * 8 + 2 * t;
        float2 a0 = *(const float2*)&Ps[r0 * PSTR + kk];
        float2 a1 = *(const float2*)&Ps[r1 * PSTR + kk];
#pragma unroll
        for (int nt = 0; nt < 8; nt++) {
            float2 b = *(const float2*)&Vs[(nt * 8 + g) * VSTR + kk];
            MMA_TF32(oa[nt], u32(a0.x), u32(a1.x), u32(a0.y), u32(a1.y),
                     u32(b.x), u32(b.y));
        }
    }

    const float inv0 = 1.f / l0, inv1 = 1.f / l1;
    float* o0p = Xr + (size_t)(win * Wc + r0) * Dc + h * HDc;
    float* o1p = Xr + (size_t)(win * Wc + r1) * Dc + h * HDc;
#pragma unroll
    for (int nt = 0; nt < 8; nt++) {
        o0p[nt * 8 + pc0] = tf32f(oa[nt][0] * inv0);
        o0p[nt * 8 + pc1] = tf32f(oa[nt][1] * inv0);
        o1p[nt * 8 + pc0] = tf32f(oa[nt][2] * inv1);
        o1p[nt * 8 + pc1] = tf32f(oa[nt][3] * inv1);
    }
}

// ---------------------------------------------------------------------------
// Global attention over 32 gathered tokens (fp32 exact). grid (B, H), 32 thr.
// ---------------------------------------------------------------------------
__global__ __launch_bounds__(32) void global_attn_kernel(
    const float* __restrict__ Qp, const float* __restrict__ Kp,
    const float* __restrict__ Vp, const int* __restrict__ gidx,
    float* __restrict__ GO)
{
    __shared__ __align__(16) float Ks[32 * 64];
    __shared__ __align__(16) float Vs[32 * 64];
    __shared__ int sidx[32];

    const int b = blockIdx.x, h = blockIdx.y, tid = threadIdx.x;
    sidx[tid] = gidx[tid];
    __syncthreads();

    for (int idx = tid; idx < 32 * 64; idx += 32) {
        int rr = idx >> 6, c = idx & 63;
        size_t gg = ((size_t)b * Sc + sidx[rr]) * Dc + h * HDc + c;
        Ks[idx] = Kp[gg];
        Vs[idx] = Vp[gg];
    }
    __syncthreads();

    const int i = tid;
    size_t qoff = ((size_t)b * Sc + sidx[i]) * Dc + h * HDc;
    float q[64];
#pragma unroll
    for (int d = 0; d < 64; d++) q[d] = Qp[qoff + d];

    float s[32];
    float mx = -1e30f;
    for (int j = 0; j < 32; j++) {
        float a = 0.f;
#pragma unroll
        for (int d = 0; d < 64; d++) a += q[d] * Ks[j * 64 + d];
        a *= 0.125f;
        s[j] = a;
        mx = fmaxf(mx, a);
    }
    float l = 0.f;
    for (int j = 0; j < 32; j++) { s[j] = __expf(s[j] - mx); l += s[j]; }

    float acc[64];
#pragma unroll
    for (int d = 0; d < 64; d++) acc[d] = 0.f;
    for (int j = 0; j < 32; j++) {
        float p = s[j];
#pragma unroll
        for (int d = 0; d < 64; d++) acc[d] += p * Vs[j * 64 + d];
    }
    float inv = 1.f / l;
    float* o = GO + ((size_t)(b * 32 + i)) * Dc + h * HDc;
#pragma unroll
    for (int d = 0; d < 64; d++) o[d] = acc[d] * inv;
}

// ---------------------------------------------------------------------------
// Project 128 global rows with Wo (fp32 exact), scatter into Y.
// ---------------------------------------------------------------------------
__global__ __launch_bounds__(256) void global_proj_kernel(
    const float* __restrict__ GO, const float* __restrict__ Wo,
    const float* __restrict__ bo, const int* __restrict__ gidx,
    float* __restrict__ Y)
{
    __shared__ __align__(16) float xr[Dc];
    const int row = blockIdx.x;
    const int nb = blockIdx.y;
    const int tid = threadIdx.x;

    for (int i = tid; i < Dc; i += 256) xr[i] = GO[(size_t)row * Dc + i];
    __syncthreads();

    const int n = nb * 256 + tid;
    const float4* wr = (const float4*)(Wo + (size_t)n * Dc);
    const float4* x4 = (const float4*)xr;
    float s0 = 0.f, s1 = 0.f, s2 = 0.f, s3 = 0.f;
#pragma unroll 8
    for (int k = 0; k < Dc / 4; k++) {
        float4 w = wr[k];
        float4 x = x4[k];
        s0 += w.x * x.x; s1 += w.y * x.y; s2 += w.z * x.z; s3 += w.w * x.w;
    }
    float sum = s0 + s1 + s2 + s3 + bo[n];

    const int b = row >> 5, i = row & 31;
    const int tok = gidx[i];
    Y[((size_t)b * Sc + tok) * Dc + n] = sum;
}

// ---------------------------------------------------------------------------
extern "C" void kernel_launch(void* const* d_in, const int* in_sizes, int n_in,
                              void* d_out, int out_size)
{
    const float* query = (const float*)d_in[0];
    const float* key   = (const float*)d_in[1];
    const float* value = (const float*)d_in[2];
    const float* Wq = (const float*)d_in[3];
    const float* bq = (const float*)d_in[4];
    const float* Wk = (const float*)d_in[5];
    const float* bk = (const float*)d_in[6];
    const float* Wv = (const float*)d_in[7];
    const float* bv = (const float*)d_in[8];
    const float* Wo = (const float*)d_in[9];
    const float* bo = (const float*)d_in[10];
    const int* gidx = (const int*)d_in[11];
    float* out = (float*)d_out;

    float *QKVb, *Xb, *Wr, *GOb;
    cudaGetSymbolAddress((void**)&QKVb, g_QKV);
    cudaGetSymbolAddress((void**)&Xb, g_X);
    cudaGetSymbolAddress((void**)&Wr, g_Wr);
    cudaGetSymbolAddress((void**)&GOb, g_GO);
    float* Qb = QKVb;
    float* Kb = QKVb + MD;
    float* Vb = QKVb + 2 * MD;

    cudaFuncSetAttribute(gemm_tf32_batch_kernel,
                         cudaFuncAttributeMaxDynamicSharedMemorySize, SMEM_GEMM);
    cudaFuncSetAttribute(window_attn_mma_kernel,
                         cudaFuncAttributeMaxDynamicSharedMemorySize, SMEM_ATTN);

    const int WN8 = (int)(DD / 8);
    const int XN8 = (int)(MD / 8);
    const int WGRID = (WN8 + 255) / 256;
    const int XGRID = (XN8 + 255) / 256;

    // Round the 4 weights (one launch, y=4): dst = Wr + z*DD
    round_perm_batch_kernel<<<dim3(WGRID, 4), 256>>>(
        Wq, Wk, Wv, Wo, Wr, DD, WN8);

    // Round the 3 activations (one launch, y=3): dst = Xb + z*MD
    round_perm_batch_kernel<<<dim3(XGRID, 3), 256>>>(
        query, key, value, query, Xb, MD, XN8);

    // Q/K/V projections in ONE batched launch (z=3)
    gemm_tf32_batch_kernel<<<dim3(Dc / GBN, Mrows / GBM, 3), 256, SMEM_GEMM>>>(
        Xb, Wr, bq, bk, bv, QKVb);

    // Windowed attention (monolithic window, float4 staging)
    window_attn_mma_kernel<<<dim3(NWIN, Hc), 256, SMEM_ATTN>>>(Qb, Kb, Vb, Xb);

    // Global attention on gathered tokens (tiny; QKV ready)
    global_attn_kernel<<<dim3(Bc, Hc), 32>>>(Qb, Kb, Vb, gidx, GOb);

    // Output projection (z=1: A = Xb[0], Wt = Wr[3], Y = out)
    gemm_tf32_batch_kernel<<<dim3(Dc / GBN, Mrows / GBM, 1), 256, SMEM_GEMM>>>(
        Xb, Wr + 3 * DD, bo, bo, bo, out);

    // Global scatter must follow the final GEMM (overwrites its rows)
    global_proj_kernel<<<dim3(Bc * 32, Dc / 256), 256>>>(GOb, Wo, bo, gidx, out);
}

// round 14
// speedup vs baseline: 1.1156x; 1.0038x over previous
#include <cuda_runtime.h>
#include <cstdint>
#include <math.h>

// ---------------------------------------------------------------------------
// Problem constants
// ---------------------------------------------------------------------------
constexpr int Bc = 4;
constexpr int Sc = 4096;
constexpr int Dc = 1024;
constexpr int Hc = 16;
constexpr int HDc = 64;
constexpr int Wc = 128;
constexpr int NWIN = Bc * (Sc / Wc);   // 128 windows
constexpr int Mrows = Bc * Sc;         // 16384
constexpr size_t MD = (size_t)Mrows * Dc;
constexpr size_t DD = (size_t)Dc * Dc;

// ---------------------------------------------------------------------------
// Scratch (device globals: allocation-free rule)
// ---------------------------------------------------------------------------
__device__ __align__(128) float g_QKV[3][Mrows * Dc];  // projected Q,K,V
__device__ __align__(128) float g_X[3][Mrows * Dc];    // rounded q,k,v / attn out in [0]
__device__ __align__(128) float g_Wr[4][Dc * Dc];      // rounded+permuted weights
__device__ float g_GO[Bc * 32 * Dc];

// ---------------------------------------------------------------------------
// PTX helpers (baseline ISA: cp.async / mma.sync tf32)
// ---------------------------------------------------------------------------
__device__ __forceinline__ uint32_t smem_to_u32(const void* p) {
    uint32_t a;
    asm("{ .reg .u64 t; cvta.to.shared.u64 t, %1; cvt.u32.u64 %0, t; }"
        : "=r"(a) : "l"(p));
    return a;
}
__device__ __forceinline__ void cp_async16(uint32_t dst, const void* src) {
    asm volatile("cp.async.cg.shared.global [%0], [%1], 16;"
                 :: "r"(dst), "l"(src));
}
#define CP_COMMIT() asm volatile("cp.async.commit_group;" ::: "memory")
#define CP_WAIT(n)  asm volatile("cp.async.wait_group %0;" :: "n"(n) : "memory")

__device__ __forceinline__ float tf32f(float x) {
    uint32_t r;
    asm("cvt.rna.tf32.f32 %0, %1;" : "=r"(r) : "f"(x));
    return __uint_as_float(r);
}
__device__ __forceinline__ uint32_t u32(float x) { return __float_as_uint(x); }

#define MMA_TF32(d, a0v, a1v, a2v, a3v, b0v, b1v) \
    asm volatile("mma.sync.aligned.m16n8k8.row.col.f32.tf32.tf32.f32 " \
        "{%0,%1,%2,%3}, {%4,%5,%6,%7}, {%8,%9}, {%0,%1,%2,%3};" \
        : "+f"((d)[0]), "+f"((d)[1]), "+f"((d)[2]), "+f"((d)[3]) \
        : "r"(a0v), "r"(a1v), "r"(a2v), "r"(a3v), "r"(b0v), "r"(b1v))

// permutation within each 8-element k-group: k -> 2*(k&3) + (k>>2)
__device__ __forceinline__ int permc(int j) { return ((j & 3) << 1) | ((j >> 2) & 1); }

// ---------------------------------------------------------------------------
// Batched fp32 -> tf32-rounded + k-permuted round pass.
// ---------------------------------------------------------------------------
__global__ __launch_bounds__(256) void round_perm_batch_kernel(
    const float* __restrict__ s0, const float* __restrict__ s1,
    const float* __restrict__ s2, const float* __restrict__ s3,
    float* __restrict__ dbase, size_t dstride, int n8)
{
    int i = blockIdx.x * 256 + threadIdx.x;
    if (i >= n8) return;
    const int z = blockIdx.y;
    const float* src = (z == 0) ? s0 : (z == 1) ? s1 : (z == 2) ? s2 : s3;
    float* y = dbase + (size_t)z * dstride;
    const float4* xp = (const float4*)src;
    float4 v0 = xp[2 * i], v1 = xp[2 * i + 1];
    float4 o0, o1;
    o0.x = tf32f(v0.x); o0.y = tf32f(v1.x); o0.z = tf32f(v0.y); o0.w = tf32f(v1.y);
    o1.x = tf32f(v0.z); o1.y = tf32f(v1.z); o1.z = tf32f(v0.w); o1.w = tf32f(v1.w);
    ((float4*)y)[2 * i] = o0;
    ((float4*)y)[2 * i + 1] = o1;
}

// ---------------------------------------------------------------------------
// tf32 mma GEMM: Y[m,n] = sum_k X[m,k]*Wt[n,k] + bias[n]
// Inputs pre-rounded & k-permuted. BM=BN=128, BK=32, 256 threads, 8 warps
// (2x4 grid, 64x32 warp tiles). LDS.64 frags, ROWF=40 pad. 2 CTAs/SM.
// Batched over blockIdx.z: A/Wt/Y by stride arithmetic, bias by ternary.
// ---------------------------------------------------------------------------
constexpr int GBM = 128, GBN = 128, GBK = 32;
constexpr int ROWF = 40;                        // floats per smem row
constexpr int TILE_B = 128 * ROWF * 4;          // 20480 B per matrix tile
constexpr int STAGE_B = 2 * TILE_B;             // 40960
constexpr int SMEM_GEMM = 2 * STAGE_B;          // 81920
constexpr int NCHUNK = Dc / GBK;                // 32

__global__ __launch_bounds__(256, 2) void gemm_tf32_batch_kernel(
    const float* __restrict__ Xbase, const float* __restrict__ Wbase,
    const float* __restrict__ bias0, const float* __restrict__ bias1,
    const float* __restrict__ bias2, float* __restrict__ Ybase)
{
    extern __shared__ __align__(128) char smem[];
    const uint32_t sbase = smem_to_u32(smem);
    const int z = blockIdx.z;
    const float* __restrict__ A = Xbase + (size_t)z * MD;
    const float* __restrict__ Bm = Wbase + (size_t)z * DD;
    const float* __restrict__ bias = (z == 0) ? bias0 : (z == 1) ? bias1 : bias2;
    float* __restrict__ Y = Ybase + (size_t)z * MD;

    const int tid = threadIdx.x;
    const int lane = tid & 31;
    const int wid = tid >> 5;
    const int wm = wid >> 2;        // 0..1 -> 64-row slab
    const int wn = wid & 3;         // 0..3 -> 32-col slab
    const int m0 = blockIdx.y * GBM;
    const int n0 = blockIdx.x * GBN;
    const int g = lane >> 2;        // 0..7
    const int t = lane & 3;         // 0..3

    float acc[4][4][4];
#pragma unroll
    for (int mi = 0; mi < 4; mi++)
#pragma unroll
        for (int nt = 0; nt < 4; nt++)
#pragma unroll
            for (int e = 0; e < 4; e++) acc[mi][nt][e] = 0.f;

    auto issue = [&](int c, int s) {
        const int k0 = c * GBK;
        const uint32_t sb = sbase + s * STAGE_B;
#pragma unroll
        for (int i = 0; i < 4; i++) {               // A: 128 rows x 8 chunks
            int idx = tid + i * 256;                // 0..1023
            int r = idx >> 3, ch = idx & 7;
            cp_async16(sb + r * (ROWF * 4) + ch * 16,
                       A + (size_t)(m0 + r) * Dc + k0 + ch * 4);
        }
#pragma unroll
        for (int i = 0; i < 4; i++) {               // B
            int idx = tid + i * 256;
            int r = idx >> 3, ch = idx & 7;
            cp_async16(sb + TILE_B + r * (ROWF * 4) + ch * 16,
                       Bm + (size_t)(n0 + r) * Dc + k0 + ch * 4);
        }
        CP_COMMIT();
    };

    issue(0, 0);
    issue(1, 1);

    for (int c = 0; c < NCHUNK; c++) {
        const int s = c & 1;
        if (c < NCHUNK - 2) { CP_WAIT(1); } else { CP_WAIT(0); }
        __syncthreads();

        const float* As = (const float*)(smem + s * STAGE_B);
        const float* Bs = (const float*)(smem + s * STAGE_B + TILE_B);

#pragma unroll
        for (int ks = 0; ks < 4; ks++) {
            const int kk = ks * 8;
            float2 bf[4];
#pragma unroll
            for (int nt = 0; nt < 4; nt++)
                bf[nt] = *(const float2*)&Bs[(wn * 32 + nt * 8 + g) * ROWF + kk + 2 * t];
#pragma unroll
            for (int mi = 0; mi < 4; mi++) {
                const int mr = wm * 64 + mi * 16 + g;
                float2 a0 = *(const float2*)&As[mr * ROWF + kk + 2 * t];
                float2 a1 = *(const float2*)&As[(mr + 8) * ROWF + kk + 2 * t];
#pragma unroll
                for (int nt = 0; nt < 4; nt++)
                    MMA_TF32(acc[mi][nt], u32(a0.x), u32(a1.x), u32(a0.y), u32(a1.y),
                             u32(bf[nt].x), u32(bf[nt].y));
            }
        }
        __syncthreads();
        if (c + 2 < NCHUNK) issue(c + 2, s);
    }

    // Epilogue: registers -> gmem with fused bias (float2, coalesced)
#pragma unroll
    for (int nt = 0; nt < 4; nt++) {
        const int n = n0 + wn * 32 + nt * 8 + 2 * t;
        const float b0 = bias[n], b1 = bias[n + 1];
#pragma unroll
        for (int mi = 0; mi < 4; mi++) {
            const int r0 = m0 + wm * 64 + mi * 16 + g;
            float2 v0, v1;
            v0.x = acc[mi][nt][0] + b0; v0.y = acc[mi][nt][1] + b1;
            v1.x = acc[mi][nt][2] + b0; v1.y = acc[mi][nt][3] + b1;
            *(float2*)&Y[(size_t)r0 * Dc + n] = v0;
            *(float2*)&Y[(size_t)(r0 + 8) * Dc + n] = v1;
        }
    }
}

// ---------------------------------------------------------------------------
// Windowed attention via tensor cores (monolithic window, float4 staging,
// conflict-tuned strides: QSTR=76 (row stride = 12 mod 32 -> 2-way staging),
// VSTR=PSTR=138 (stride*4 = 8 mod 32 -> 4-way V staging vs 16-way before;
// even strides keep all float2 smem accesses 8B-aligned).
// grid (NWIN, H), 256 threads (8 warps, 16 Q-rows each). Exact softmax.
// Output tf32-rounded + k-permuted into Xr for the final GEMM.
// ---------------------------------------------------------------------------
constexpr int QSTR = 76;    // row stride (floats) for Qh/Ql/Ks  [row][d]
constexpr int VSTR = 138;   // row stride for Vs [d][key]
constexpr int PSTR = 138;   // row stride for Ps [row][key]
constexpr int OFF_QH = 0;
constexpr int OFF_QL = OFF_QH + 128 * QSTR;     // 9728
constexpr int OFF_K  = OFF_QL + 128 * QSTR;     // 19456
constexpr int OFF_V  = OFF_K + 128 * QSTR;      // 29184
constexpr int OFF_P  = OFF_V + 64 * VSTR;       // 38016
constexpr int SMEM_ATTN = (OFF_P + 128 * PSTR) * 4;  // 222720 B

__global__ __launch_bounds__(256, 1) void window_attn_mma_kernel(
    const float* __restrict__ Qp, const float* __restrict__ Kp,
    const float* __restrict__ Vp, float* __restrict__ Xr)
{
    extern __shared__ __align__(16) float sm[];
    float* Qh = sm + OFF_QH;
    float* Ql = sm + OFF_QL;
    float* Ks = sm + OFF_K;
    float* Vs = sm + OFF_V;
    float* Ps = sm + OFF_P;

    const int win = blockIdx.x;
    const int h = blockIdx.y;
    const size_t base = (size_t)win * Wc * Dc + h * HDc;
    const int tid = threadIdx.x;

    // Stage Q (hi/lo split), K, V — float4 loads, tf32 rounding, permuted STS.
#pragma unroll
    for (int it = 0; it < 8; it++) {
        int idx = tid + it * 256;                // 0..2047
        int row = idx >> 4;                      // 0..127
        int col4 = (idx & 15) << 2;              // 0,4,...,60
        int pcb = (col4 & ~7) | ((col4 & 4) ? 1 : 0);
        size_t ga = base + (size_t)row * Dc + col4;
        float4 qv = *(const float4*)(Qp + ga);
        float4 kv = *(const float4*)(Kp + ga);
        float4 vv = *(const float4*)(Vp + ga);

        float h0 = tf32f(qv.x), h1 = tf32f(qv.y);
        float h2 = tf32f(qv.z), h3 = tf32f(qv.w);
        float* qh = &Qh[row * QSTR + pcb];
        float* ql = &Ql[row * QSTR + pcb];
        float* ks = &Ks[row * QSTR + pcb];
        qh[0] = h0; qh[2] = h1; qh[4] = h2; qh[6] = h3;
        ql[0] = tf32f(qv.x - h0); ql[2] = tf32f(qv.y - h1);
        ql[4] = tf32f(qv.z - h2); ql[6] = tf32f(qv.w - h3);
        ks[0] = tf32f(kv.x); ks[2] = tf32f(kv.y);
        ks[4] = tf32f(kv.z); ks[6] = tf32f(kv.w);

        int pk = (row & ~7) | permc(row & 7);
        Vs[(col4 + 0) * VSTR + pk] = tf32f(vv.x);
        Vs[(col4 + 1) * VSTR + pk] = tf32f(vv.y);
        Vs[(col4 + 2) * VSTR + pk] = tf32f(vv.z);
        Vs[(col4 + 3) * VSTR + pk] = tf32f(vv.w);
    }
    __syncthreads();

    const int w = tid >> 5;
    const int lane = tid & 31;
    const int g = lane >> 2, t = lane & 3;
    const int r0 = w * 16 + g, r1 = r0 + 8;
    const int pc0 = permc(2 * t), pc1 = permc(2 * t + 1);

    // ---- S = Q*K^T (2-pass: Qhi + Qlo) ----
    float sa[16][4];
#pragma unroll
    for (int nt = 0; nt < 16; nt++)
#pragma unroll
        for (int e = 0; e < 4; e++) sa[nt][e] = 0.f;

#pragma unroll
    for (int kt = 0; kt < 8; kt++) {
        const int kk = kt * 8 + 2 * t;
        float2 ah0 = *(const float2*)&Qh[r0 * QSTR + kk];
        float2 ah1 = *(const float2*)&Qh[r1 * QSTR + kk];
        float2 al0 = *(const float2*)&Ql[r0 * QSTR + kk];
        float2 al1 = *(const float2*)&Ql[r1 * QSTR + kk];
#pragma unroll
        for (int nt = 0; nt < 16; nt++) {
            float2 b = *(const float2*)&Ks[(nt * 8 + g) * QSTR + kk];
            MMA_TF32(sa[nt], u32(ah0.x), u32(ah1.x), u32(ah0.y), u32(ah1.y),
                     u32(b.x), u32(b.y));
            MMA_TF32(sa[nt], u32(al0.x), u32(al1.x), u32(al0.y), u32(al1.y),
                     u32(b.x), u32(b.y));
        }
    }

    // ---- softmax (rows r0, r1) ----
    float mx0 = -1e30f, mx1 = -1e30f;
#pragma unroll
    for (int nt = 0; nt < 16; nt++) {
#pragma unroll
        for (int e = 0; e < 4; e++) sa[nt][e] *= 0.125f;
        mx0 = fmaxf(mx0, fmaxf(sa[nt][0], sa[nt][1]));
        mx1 = fmaxf(mx1, fmaxf(sa[nt][2], sa[nt][3]));
    }
    mx0 = fmaxf(mx0, __shfl_xor_sync(0xffffffffu, mx0, 1));
    mx0 = fmaxf(mx0, __shfl_xor_sync(0xffffffffu, mx0, 2));
    mx1 = fmaxf(mx1, __shfl_xor_sync(0xffffffffu, mx1, 1));
    mx1 = fmaxf(mx1, __shfl_xor_sync(0xffffffffu, mx1, 2));

    float l0 = 0.f, l1 = 0.f;
#pragma unroll
    for (int nt = 0; nt < 16; nt++) {
        float p00 = __expf(sa[nt][0] - mx0);
        float p01 = __expf(sa[nt][1] - mx0);
        float p10 = __expf(sa[nt][2] - mx1);
        float p11 = __expf(sa[nt][3] - mx1);
        l0 += p00 + p01;
        l1 += p10 + p11;
        Ps[r0 * PSTR + nt * 8 + pc0] = tf32f(p00);
        Ps[r0 * PSTR + nt * 8 + pc1] = tf32f(p01);
        Ps[r1 * PSTR + nt * 8 + pc0] = tf32f(p10);
        Ps[r1 * PSTR + nt * 8 + pc1] = tf32f(p11);
    }
    l0 += __shfl_xor_sync(0xffffffffu, l0, 1);
    l0 += __shfl_xor_sync(0xffffffffu, l0, 2);
    l1 += __shfl_xor_sync(0xffffffffu, l1, 1);
    l1 += __shfl_xor_sync(0xffffffffu, l1, 2);
    __syncwarp();

    // ---- O = P*V ----
    float oa[8][4];
#pragma unroll
    for (int nt = 0; nt < 8; nt++)
#pragma unroll
        for (int e = 0; e < 4; e++) oa[nt][e] = 0.f;

#pragma unroll
    for (int kt = 0; kt < 16; kt++) {
        const int kk = kt * 8 + 2 * t;
        float2 a0 = *(const float2*)&Ps[r0 * PSTR + kk];
        float2 a1 = *(const float2*)&Ps[r1 * PSTR + kk];
#pragma unroll
        for (int nt = 0; nt < 8; nt++) {
            float2 b = *(const float2*)&Vs[(nt * 8 + g) * VSTR + kk];
            MMA_TF32(oa[nt], u32(a0.x), u32(a1.x), u32(a0.y), u32(a1.y),
                     u32(b.x), u32(b.y));
        }
    }

    const float inv0 = 1.f / l0, inv1 = 1.f / l1;
    float* o0p = Xr + (size_t)(win * Wc + r0) * Dc + h * HDc;
    float* o1p = Xr + (size_t)(win * Wc + r1) * Dc + h * HDc;
#pragma unroll
    for (int nt = 0; nt < 8; nt++) {
        o0p[nt * 8 + pc0] = tf32f(oa[nt][0] * inv0);
        o0p[nt * 8 + pc1] = tf32f(oa[nt][1] * inv0);
        o1p[nt * 8 + pc0] = tf32f(oa[nt][2] * inv1);
        o1p[nt * 8 + pc1] = tf32f(oa[nt][3] * inv1);
    }
}

// ---------------------------------------------------------------------------
// Global attention over 32 gathered tokens (fp32 exact). grid (B, H), 32 thr.
// ---------------------------------------------------------------------------
__global__ __launch_bounds__(32) void global_attn_kernel(
    const float* __restrict__ Qp, const float* __restrict__ Kp,
    const float* __restrict__ Vp, const int* __restrict__ gidx,
    float* __restrict__ GO)
{
    __shared__ __align__(16) float Ks[32 * 64];
    __shared__ __align__(16) float Vs[32 * 64];
    __shared__ int sidx[32];

    const int b = blockIdx.x, h = blockIdx.y, tid = threadIdx.x;
    sidx[tid] = gidx[tid];
    __syncthreads();

    for (int idx = tid; idx < 32 * 64; idx += 32) {
        int rr = idx >> 6, c = idx & 63;
        size_t gg = ((size_t)b * Sc + sidx[rr]) * Dc + h * HDc + c;
        Ks[idx] = Kp[gg];
        Vs[idx] = Vp[gg];
    }
    __syncthreads();

    const int i = tid;
    size_t qoff = ((size_t)b * Sc + sidx[i]) * Dc + h * HDc;
    float q[64];
#pragma unroll
    for (int d = 0; d < 64; d++) q[d] = Qp[qoff + d];

    float s[32];
    float mx = -1e30f;
    for (int j = 0; j < 32; j++) {
        float a = 0.f;
#pragma unroll
        for (int d = 0; d < 64; d++) a += q[d] * Ks[j * 64 + d];
        a *= 0.125f;
        s[j] = a;
        mx = fmaxf(mx, a);
    }
    float l = 0.f;
    for (int j = 0; j < 32; j++) { s[j] = __expf(s[j] - mx); l += s[j]; }

    float acc[64];
#pragma unroll
    for (int d = 0; d < 64; d++) acc[d] = 0.f;
    for (int j = 0; j < 32; j++) {
        float p = s[j];
#pragma unroll
        for (int d = 0; d < 64; d++) acc[d] += p * Vs[j * 64 + d];
    }
    float inv = 1.f / l;
    float* o = GO + ((size_t)(b * 32 + i)) * Dc + h * HDc;
#pragma unroll
    for (int d = 0; d < 64; d++) o[d] = acc[d] * inv;
}

// ---------------------------------------------------------------------------
// Project 128 global rows with Wo (fp32 exact), scatter into Y.
// ---------------------------------------------------------------------------
__global__ __launch_bounds__(256) void global_proj_kernel(
    const float* __restrict__ GO, const float* __restrict__ Wo,
    const float* __restrict__ bo, const int* __restrict__ gidx,
    float* __restrict__ Y)
{
    __shared__ __align__(16) float xr[Dc];
    const int row = blockIdx.x;
    const int nb = blockIdx.y;
    const int tid = threadIdx.x;

    for (int i = tid; i < Dc; i += 256) xr[i] = GO[(size_t)row * Dc + i];
    __syncthreads();

    const int n = nb * 256 + tid;
    const float4* wr = (const float4*)(Wo + (size_t)n * Dc);
    const float4* x4 = (const float4*)xr;
    float s0 = 0.f, s1 = 0.f, s2 = 0.f, s3 = 0.f;
#pragma unroll 8
    for (int k = 0; k < Dc / 4; k++) {
        float4 w = wr[k];
        float4 x = x4[k];
        s0 += w.x * x.x; s1 += w.y * x.y; s2 += w.z * x.z; s3 += w.w * x.w;
    }
    float sum = s0 + s1 + s2 + s3 + bo[n];

    const int b = row >> 5, i = row & 31;
    const int tok = gidx[i];
    Y[((size_t)b * Sc + tok) * Dc + n] = sum;
}

// ---------------------------------------------------------------------------
extern "C" void kernel_launch(void* const* d_in, const int* in_sizes, int n_in,
                              void* d_out, int out_size)
{
    const float* query = (const float*)d_in[0];
    const float* key   = (const float*)d_in[1];
    const float* value = (const float*)d_in[2];
    const float* Wq = (const float*)d_in[3];
    const float* bq = (const float*)d_in[4];
    const float* Wk = (const float*)d_in[5];
    const float* bk = (const float*)d_in[6];
    const float* Wv = (const float*)d_in[7];
    const float* bv = (const float*)d_in[8];
    const float* Wo = (const float*)d_in[9];
    const float* bo = (const float*)d_in[10];
    const int* gidx = (const int*)d_in[11];
    float* out = (float*)d_out;

    float *QKVb, *Xb, *Wr, *GOb;
    cudaGetSymbolAddress((void**)&QKVb, g_QKV);
    cudaGetSymbolAddress((void**)&Xb, g_X);
    cudaGetSymbolAddress((void**)&Wr, g_Wr);
    cudaGetSymbolAddress((void**)&GOb, g_GO);
    float* Qb = QKVb;
    float* Kb = QKVb + MD;
    float* Vb = QKVb + 2 * MD;

    cudaFuncSetAttribute(gemm_tf32_batch_kernel,
                         cudaFuncAttributeMaxDynamicSharedMemorySize, SMEM_GEMM);
    cudaFuncSetAttribute(window_attn_mma_kernel,
                         cudaFuncAttributeMaxDynamicSharedMemorySize, SMEM_ATTN);

    const int WN8 = (int)(DD / 8);
    const int XN8 = (int)(MD / 8);
    const int WGRID = (WN8 + 255) / 256;
    const int XGRID = (XN8 + 255) / 256;

    // Round the 4 weights (one launch, y=4): dst = Wr + z*DD
    round_perm_batch_kernel<<<dim3(WGRID, 4), 256>>>(
        Wq, Wk, Wv, Wo, Wr, DD, WN8);

    // Round the 3 activations (one launch, y=3): dst = Xb + z*MD
    round_perm_batch_kernel<<<dim3(XGRID, 3), 256>>>(
        query, key, value, query, Xb, MD, XN8);

    // Q/K/V projections in ONE batched launch (z=3)
    gemm_tf32_batch_kernel<<<dim3(Dc / GBN, Mrows / GBM, 3), 256, SMEM_GEMM>>>(
        Xb, Wr, bq, bk, bv, QKVb);

    // Windowed attention (monolithic window, float4 staging, tuned strides)
    window_attn_mma_kernel<<<dim3(NWIN, Hc), 256, SMEM_ATTN>>>(Qb, Kb, Vb, Xb);

    // Global attention on gathered tokens (tiny; QKV ready)
    global_attn_kernel<<<dim3(Bc, Hc), 32>>>(Qb, Kb, Vb, gidx, GOb);

    // Output projection (z=1: A = Xb[0], Wt = Wr[3], Y = out)
    gemm_tf32_batch_kernel<<<dim3(Dc / GBN, Mrows / GBM, 1), 256, SMEM_GEMM>>>(
        Xb, Wr + 3 * DD, bo, bo, bo, out);

    // Global scatter must follow the final GEMM (overwrites its rows)
    global_proj_kernel<<<dim3(Bc * 32, Dc / 256), 256>>>(GOb, Wo, bo, gidx, out);
}